// round 1
// baseline (speedup 1.0000x reference)
#include <cuda_runtime.h>

#define NNODES 50000
#define EEDGES 1600000
#define DHID 128
#define DNF 128
#define DNG 64
#define TE 64
#define NTHREADS 256
#define LN2 0.69314718055994530942f
#define FPI 3.14159265358979323846f

static_assert(EEDGES % TE == 0, "edge tiles must divide E");

// Scratch (static device arrays: allocation-free per harness rules)
__device__ float g_h[(size_t)NNODES * DNF];    // x @ lin1_w
__device__ float g_agg[(size_t)NNODES * DNF];  // segment_sum accumulator

// ShiftedSoftplus: softplus(v) - ln2, numerically stable.
// __logf abs err ~2^-21.4 on [1,2]; __expf ~2 ulp -> plenty for 1e-3 rel.
__device__ __forceinline__ float ssp_f(float v) {
    return fmaxf(v, 0.0f) + __logf(1.0f + __expf(-fabsf(v))) - LN2;
}

__device__ __forceinline__ void red_add_v4(float* p, float a, float b, float c, float d) {
    asm volatile("red.global.add.v4.f32 [%0], {%1, %2, %3, %4};"
                 :: "l"(p), "f"(a), "f"(b), "f"(c), "f"(d) : "memory");
}

// acc[4][8] += A^T(K x 64, row-pad 65) * B(K x 128)
// thread (e0 = tid>>4, c0 = (tid&15)*8): rows {e0, e0+16, e0+32, e0+48}, cols c0..c0+7
__device__ __forceinline__ void mm_tile(const float* __restrict__ As,
                                        const float* __restrict__ Bs,
                                        int K, int e0, int c0, float acc[4][8]) {
#pragma unroll 4
    for (int k = 0; k < K; ++k) {
        const float* ar = As + k * 65;
        float aa0 = ar[e0];
        float aa1 = ar[e0 + 16];
        float aa2 = ar[e0 + 32];
        float aa3 = ar[e0 + 48];
        float4 bv0 = *(const float4*)(Bs + k * DNF + c0);
        float4 bv1 = *(const float4*)(Bs + k * DNF + c0 + 4);
        float bb[8] = {bv0.x, bv0.y, bv0.z, bv0.w, bv1.x, bv1.y, bv1.z, bv1.w};
#pragma unroll
        for (int j = 0; j < 8; ++j) {
            acc[0][j] = fmaf(aa0, bb[j], acc[0][j]);
            acc[1][j] = fmaf(aa1, bb[j], acc[1][j]);
            acc[2][j] = fmaf(aa2, bb[j], acc[2][j]);
            acc[3][j] = fmaf(aa3, bb[j], acc[3][j]);
        }
    }
}

// ---------------- Kernel 1: h = x @ lin1_w, zero g_agg ----------------
extern "C" __global__ void __launch_bounds__(NTHREADS, 1)
k_proj_zero(const float* __restrict__ x, const float* __restrict__ w1) {
    extern __shared__ float sm[];
    float* sW = sm;               // 128*128
    float* sX = sW + DHID * DNF;  // 128*65 (transposed tile)
    const int tid = threadIdx.x;
    const int e0 = tid >> 4;
    const int c0 = (tid & 15) * 8;

    for (int i = tid; i < DHID * DNF / 4; i += NTHREADS)
        ((float4*)sW)[i] = ((const float4*)w1)[i];

    const int ntiles = (NNODES + TE - 1) / TE;
    for (int tile = blockIdx.x; tile < ntiles; tile += gridDim.x) {
        const int r0 = tile * TE;
        __syncthreads();  // also orders weight load before first use
        for (int idx = tid; idx < TE * DHID; idx += NTHREADS) {
            int e = idx >> 7, k = idx & 127;
            int r = r0 + e;
            sX[k * 65 + e] = (r < NNODES) ? x[(size_t)r * DHID + k] : 0.0f;
        }
        __syncthreads();
        float acc[4][8];
#pragma unroll
        for (int i = 0; i < 4; ++i)
#pragma unroll
            for (int j = 0; j < 8; ++j) acc[i][j] = 0.0f;
        mm_tile(sX, sW, DHID, e0, c0, acc);
#pragma unroll
        for (int i = 0; i < 4; ++i) {
            int r = r0 + e0 + 16 * i;
            if (r < NNODES) {
                *(float4*)(g_h + (size_t)r * DNF + c0) =
                    make_float4(acc[i][0], acc[i][1], acc[i][2], acc[i][3]);
                *(float4*)(g_h + (size_t)r * DNF + c0 + 4) =
                    make_float4(acc[i][4], acc[i][5], acc[i][6], acc[i][7]);
                *(float4*)(g_agg + (size_t)r * DNF + c0) = make_float4(0.f, 0.f, 0.f, 0.f);
                *(float4*)(g_agg + (size_t)r * DNF + c0 + 4) = make_float4(0.f, 0.f, 0.f, 0.f);
            }
        }
    }
}

// ---------------- Kernel 2: edge MLP + envelope + gather/scatter ----------------
extern "C" __global__ void __launch_bounds__(NTHREADS, 1)
k_edge(const float* __restrict__ edge_attr, const int* __restrict__ ei,
       const float* __restrict__ elen,
       const float* __restrict__ w1, const float* __restrict__ b1,
       const float* __restrict__ w2, const float* __restrict__ b2) {
    extern __shared__ float sm[];
    float* sW1 = sm;               // 64*128
    float* sW2 = sW1 + DNG * DNF;  // 128*128
    float* sA  = sW2 + DNF * DNF;  // 64*65   (edge_attr^T tile)
    float* sT  = sA + DNG * 65;    // 128*65  (ssp(T)^T tile)
    float* sB1 = sT + DNF * 65;    // 128
    float* sB2 = sB1 + DNF;        // 128
    float* sC  = sB2 + DNF;        // 64
    int* sSrc = (int*)(sC + TE);   // 64
    int* sDst = sSrc + TE;         // 64

    const int tid = threadIdx.x;
    const int e0 = tid >> 4;
    const int c0 = (tid & 15) * 8;

    for (int i = tid; i < DNG * DNF / 4; i += NTHREADS)
        ((float4*)sW1)[i] = ((const float4*)w1)[i];
    for (int i = tid; i < DNF * DNF / 4; i += NTHREADS)
        ((float4*)sW2)[i] = ((const float4*)w2)[i];
    if (tid < DNF) { sB1[tid] = b1[tid]; sB2[tid] = b2[tid]; }

    const int ntiles = EEDGES / TE;
    for (int tile = blockIdx.x; tile < ntiles; tile += gridDim.x) {
        const int eg0 = tile * TE;
        __syncthreads();  // WAR on sA/sT from previous tile + weight visibility
        for (int idx = tid; idx < TE * DNG; idx += NTHREADS) {
            int e = idx >> 6, g = idx & 63;
            sA[g * 65 + e] = edge_attr[(size_t)(eg0 + e) * DNG + g];
        }
        if (tid < TE) {
            int e = eg0 + tid;
            sSrc[tid] = ei[e];
            sDst[tid] = ei[EEDGES + e];
            float L = elen[e];
            float cv = 0.5f * (__cosf(L * (FPI / 10.0f)) + 1.0f);
            sC[tid] = (L <= 10.0f && L >= 0.0f) ? cv : 0.0f;
        }
        __syncthreads();

        float acc[4][8];
#pragma unroll
        for (int i = 0; i < 4; ++i)
#pragma unroll
            for (int j = 0; j < 8; ++j) acc[i][j] = 0.0f;
        mm_tile(sA, sW1, DNG, e0, c0, acc);  // T = A @ W1

        // ssp(T + b1), stored transposed for stage 2
#pragma unroll
        for (int j = 0; j < 8; ++j) {
            float bv = sB1[c0 + j];
#pragma unroll
            for (int i = 0; i < 4; ++i)
                sT[(c0 + j) * 65 + e0 + 16 * i] = ssp_f(acc[i][j] + bv);
        }
        __syncthreads();

#pragma unroll
        for (int i = 0; i < 4; ++i)
#pragma unroll
            for (int j = 0; j < 8; ++j) acc[i][j] = 0.0f;
        mm_tile(sT, sW2, DNF, e0, c0, acc);  // W = ssp(T) @ W2

        float bb2[8];
#pragma unroll
        for (int j = 0; j < 8; ++j) bb2[j] = sB2[c0 + j];

        // epilogue: msg = (W + b2) * C * h[src], scatter-add to agg[dst]
#pragma unroll
        for (int i = 0; i < 4; ++i) {
            int el = e0 + 16 * i;
            float cv = sC[el];
            if (cv != 0.0f) {
                int s = sSrc[el], d = sDst[el];
                const float* hp = g_h + (size_t)s * DNF + c0;
                float4 h0 = *(const float4*)hp;
                float4 h1 = *(const float4*)(hp + 4);
                float* dp = g_agg + (size_t)d * DNF + c0;
                red_add_v4(dp,
                           (acc[i][0] + bb2[0]) * cv * h0.x,
                           (acc[i][1] + bb2[1]) * cv * h0.y,
                           (acc[i][2] + bb2[2]) * cv * h0.z,
                           (acc[i][3] + bb2[3]) * cv * h0.w);
                red_add_v4(dp + 4,
                           (acc[i][4] + bb2[4]) * cv * h1.x,
                           (acc[i][5] + bb2[5]) * cv * h1.y,
                           (acc[i][6] + bb2[6]) * cv * h1.z,
                           (acc[i][7] + bb2[7]) * cv * h1.w);
            }
        }
    }
}

// ---------------- Kernel 3: out = ssp(agg@lin2_w + lin2_b) @ lin_w + lin_b ----------------
extern "C" __global__ void __launch_bounds__(NTHREADS, 1)
k_out(const float* __restrict__ w2, const float* __restrict__ b2,
      const float* __restrict__ w3, const float* __restrict__ b3,
      float* __restrict__ out) {
    extern __shared__ float sm[];
    float* sW2 = sm;                // 128*128 (lin2_w)
    float* sW3 = sW2 + DNF * DHID;  // 128*128 (lin_w)
    float* sA  = sW3 + DHID * DHID; // 128*65  (agg^T tile)
    float* sT  = sA + DNF * 65;     // 128*65  (mid^T tile)
    float* sB2 = sT + DHID * 65;    // 128
    float* sB3 = sB2 + DHID;        // 128

    const int tid = threadIdx.x;
    const int e0 = tid >> 4;
    const int c0 = (tid & 15) * 8;

    for (int i = tid; i < DNF * DHID / 4; i += NTHREADS)
        ((float4*)sW2)[i] = ((const float4*)w2)[i];
    for (int i = tid; i < DHID * DHID / 4; i += NTHREADS)
        ((float4*)sW3)[i] = ((const float4*)w3)[i];
    if (tid < DHID) { sB2[tid] = b2[tid]; sB3[tid] = b3[tid]; }

    const int ntiles = (NNODES + TE - 1) / TE;
    for (int tile = blockIdx.x; tile < ntiles; tile += gridDim.x) {
        const int r0 = tile * TE;
        __syncthreads();
        for (int idx = tid; idx < TE * DNF; idx += NTHREADS) {
            int e = idx >> 7, k = idx & 127;
            int r = r0 + e;
            sA[k * 65 + e] = (r < NNODES) ? g_agg[(size_t)r * DNF + k] : 0.0f;
        }
        __syncthreads();

        float acc[4][8];
#pragma unroll
        for (int i = 0; i < 4; ++i)
#pragma unroll
            for (int j = 0; j < 8; ++j) acc[i][j] = 0.0f;
        mm_tile(sA, sW2, DNF, e0, c0, acc);

#pragma unroll
        for (int j = 0; j < 8; ++j) {
            float bv = sB2[c0 + j];
#pragma unroll
            for (int i = 0; i < 4; ++i)
                sT[(c0 + j) * 65 + e0 + 16 * i] = ssp_f(acc[i][j] + bv);
        }
        __syncthreads();

#pragma unroll
        for (int i = 0; i < 4; ++i)
#pragma unroll
            for (int j = 0; j < 8; ++j) acc[i][j] = 0.0f;
        mm_tile(sT, sW3, DHID, e0, c0, acc);

#pragma unroll
        for (int i = 0; i < 4; ++i) {
            int r = r0 + e0 + 16 * i;
            if (r < NNODES) {
                *(float4*)(out + (size_t)r * DHID + c0) =
                    make_float4(acc[i][0] + sB3[c0 + 0], acc[i][1] + sB3[c0 + 1],
                                acc[i][2] + sB3[c0 + 2], acc[i][3] + sB3[c0 + 3]);
                *(float4*)(out + (size_t)r * DHID + c0 + 4) =
                    make_float4(acc[i][4] + sB3[c0 + 4], acc[i][5] + sB3[c0 + 5],
                                acc[i][6] + sB3[c0 + 6], acc[i][7] + sB3[c0 + 7]);
            }
        }
    }
}

extern "C" void kernel_launch(void* const* d_in, const int* in_sizes, int n_in,
                              void* d_out, int out_size) {
    const float* x      = (const float*)d_in[0];
    const int*   ei     = (const int*)d_in[1];
    const float* elen   = (const float*)d_in[2];
    const float* eattr  = (const float*)d_in[3];
    const float* lin1_w = (const float*)d_in[4];
    const float* nn_w1  = (const float*)d_in[5];
    const float* nn_b1  = (const float*)d_in[6];
    const float* nn_w2  = (const float*)d_in[7];
    const float* nn_b2  = (const float*)d_in[8];
    const float* lin2_w = (const float*)d_in[9];
    const float* lin2_b = (const float*)d_in[10];
    const float* lin_w  = (const float*)d_in[11];
    const float* lin_b  = (const float*)d_in[12];
    float* out = (float*)d_out;

    size_t sm1 = (size_t)(DHID * DNF + DHID * 65) * 4;
    size_t sm2 = (size_t)(DNG * DNF + DNF * DNF + DNG * 65 + DNF * 65 + DNF + DNF + TE + 2 * TE) * 4;
    size_t sm3 = (size_t)(DNF * DHID + DHID * DHID + DNF * 65 + DHID * 65 + DHID + DHID) * 4;

    cudaFuncSetAttribute(k_proj_zero, cudaFuncAttributeMaxDynamicSharedMemorySize, (int)sm1);
    cudaFuncSetAttribute(k_edge,      cudaFuncAttributeMaxDynamicSharedMemorySize, (int)sm2);
    cudaFuncSetAttribute(k_out,       cudaFuncAttributeMaxDynamicSharedMemorySize, (int)sm3);

    k_proj_zero<<<152, NTHREADS, sm1>>>(x, lin1_w);
    k_edge<<<152, NTHREADS, sm2>>>(eattr, ei, elen, nn_w1, nn_b1, nn_w2, nn_b2);
    k_out<<<152, NTHREADS, sm3>>>(lin2_w, lin2_b, lin_w, lin_b, out);
}

// round 2
// speedup vs baseline: 1.0984x; 1.0984x over previous
#include <cuda_runtime.h>

#define NNODES 50000
#define EEDGES 1600000
#define DHID 128
#define DNF 128
#define DNG 64
#define LN2 0.69314718055994530942f
#define FPI 3.14159265358979323846f

// Scratch (static device arrays: allocation-free per harness rules)
__device__ float g_h[(size_t)NNODES * DNF];    // x @ lin1_w
__device__ float g_agg[(size_t)NNODES * DNF];  // segment_sum accumulator

// ShiftedSoftplus: softplus(v) - ln2, numerically stable.
__device__ __forceinline__ float ssp_f(float v) {
    return fmaxf(v, 0.0f) + __logf(1.0f + __expf(-fabsf(v))) - LN2;
}

__device__ __forceinline__ void red_add_v4(float* p, float a, float b, float c, float d) {
    asm volatile("red.global.add.v4.f32 [%0], {%1, %2, %3, %4};"
                 :: "l"(p), "f"(a), "f"(b), "f"(c), "f"(d) : "memory");
}

// ---- packed f32x2 helpers (FFMA2 path: only reachable via PTX) ----
__device__ __forceinline__ unsigned long long pack2(float a) {
    unsigned long long r;
    asm("mov.b64 %0, {%1, %1};" : "=l"(r) : "f"(a));
    return r;
}
__device__ __forceinline__ float2 unpack2(unsigned long long v) {
    float2 f;
    asm("mov.b64 {%0, %1}, %2;" : "=f"(f.x), "=f"(f.y) : "l"(v));
    return f;
}
__device__ __forceinline__ void fma2(unsigned long long& d, unsigned long long a,
                                     unsigned long long b) {
    asm("fma.rn.f32x2 %0, %1, %2, %0;" : "+l"(d) : "l"(a), "l"(b));
}

// acc[4][4] (f32x2 pairs) += A^T(K x TE, row stride AST) * B(K x 128)
// thread covers rows {e0, e0+RSP, e0+2RSP, e0+3RSP}, cols c0..c0+7 (4 pairs)
template <int AST, int RSP>
__device__ __forceinline__ void mm_tile2(const float* __restrict__ As,
                                         const float* __restrict__ Bs,
                                         int K, int e0, int c0,
                                         unsigned long long acc[4][4]) {
#pragma unroll 4
    for (int k = 0; k < K; ++k) {
        const float* ar = As + k * AST;
        unsigned long long a0 = pack2(ar[e0]);
        unsigned long long a1 = pack2(ar[e0 + RSP]);
        unsigned long long a2 = pack2(ar[e0 + 2 * RSP]);
        unsigned long long a3 = pack2(ar[e0 + 3 * RSP]);
        const float* br = Bs + k * DNF + c0;
        ulonglong2 b01 = *(const ulonglong2*)br;
        ulonglong2 b23 = *(const ulonglong2*)(br + 4);
        unsigned long long bb[4] = {b01.x, b01.y, b23.x, b23.y};
#pragma unroll
        for (int p = 0; p < 4; ++p) {
            fma2(acc[0][p], a0, bb[p]);
            fma2(acc[1][p], a1, bb[p]);
            fma2(acc[2][p], a2, bb[p]);
            fma2(acc[3][p], a3, bb[p]);
        }
    }
}

// ---------------- Kernel 1: h = x @ lin1_w, zero g_agg (TE=128, 512 thr) ----------------
extern "C" __global__ void __launch_bounds__(512, 1)
k_proj_zero(const float* __restrict__ x, const float* __restrict__ w1) {
    extern __shared__ float sm[];
    float* sW = sm;               // 128*128
    float* sX = sW + DHID * DNF;  // 128*129 (transposed tile)
    const int tid = threadIdx.x;
    const int e0 = tid >> 4;           // 0..31
    const int c0 = (tid & 15) * 8;

    for (int i = tid; i < DHID * DNF / 4; i += 512)
        ((float4*)sW)[i] = ((const float4*)w1)[i];

    const int ntiles = (NNODES + 127) / 128;
    for (int tile = blockIdx.x; tile < ntiles; tile += gridDim.x) {
        const int r0 = tile * 128;
        __syncthreads();
        for (int idx = tid; idx < 128 * DHID; idx += 512) {
            int e = idx >> 7, k = idx & 127;
            int r = r0 + e;
            sX[k * 129 + e] = (r < NNODES) ? x[(size_t)r * DHID + k] : 0.0f;
        }
        __syncthreads();
        unsigned long long acc[4][4];
#pragma unroll
        for (int i = 0; i < 4; ++i)
#pragma unroll
            for (int p = 0; p < 4; ++p) acc[i][p] = 0ull;
        mm_tile2<129, 32>(sX, sW, DHID, e0, c0, acc);
#pragma unroll
        for (int i = 0; i < 4; ++i) {
            int r = r0 + e0 + 32 * i;
            if (r < NNODES) {
                float2 v0 = unpack2(acc[i][0]), v1 = unpack2(acc[i][1]);
                float2 v2 = unpack2(acc[i][2]), v3 = unpack2(acc[i][3]);
                *(float4*)(g_h + (size_t)r * DNF + c0) = make_float4(v0.x, v0.y, v1.x, v1.y);
                *(float4*)(g_h + (size_t)r * DNF + c0 + 4) = make_float4(v2.x, v2.y, v3.x, v3.y);
                *(float4*)(g_agg + (size_t)r * DNF + c0) = make_float4(0.f, 0.f, 0.f, 0.f);
                *(float4*)(g_agg + (size_t)r * DNF + c0 + 4) = make_float4(0.f, 0.f, 0.f, 0.f);
            }
        }
    }
}

// ---------------- Kernel 2: edge MLP + envelope + gather/scatter (TE=128, 512 thr) --------
extern "C" __global__ void __launch_bounds__(512, 1)
k_edge(const float* __restrict__ edge_attr, const int* __restrict__ ei,
       const float* __restrict__ elen,
       const float* __restrict__ w1, const float* __restrict__ b1,
       const float* __restrict__ w2, const float* __restrict__ b2) {
    extern __shared__ float sm[];
    float* sW1 = sm;                // 64*128   = 8192
    float* sW2 = sW1 + DNG * DNF;   // 128*128  = 16384
    float* sA  = sW2 + DNF * DNF;   // 64*129   = 8256
    float* sT  = sA + DNG * 129;    // 128*129  = 16512
    float* sB1 = sT + DNF * 129;    // 128
    float* sB2 = sB1 + DNF;         // 128
    float* sC  = sB2 + DNF;         // 128
    int* sSrc = (int*)(sC + 128);   // 128
    int* sDst = sSrc + 128;         // 128

    const int tid = threadIdx.x;
    const int e0 = tid >> 4;        // 0..31
    const int c0 = (tid & 15) * 8;

    for (int i = tid; i < DNG * DNF / 4; i += 512)
        ((float4*)sW1)[i] = ((const float4*)w1)[i];
    for (int i = tid; i < DNF * DNF / 4; i += 512)
        ((float4*)sW2)[i] = ((const float4*)w2)[i];
    if (tid < DNF) { sB1[tid] = b1[tid]; sB2[tid] = b2[tid]; }

    const int ntiles = EEDGES / 128;
    for (int tile = blockIdx.x; tile < ntiles; tile += gridDim.x) {
        const int eg0 = tile * 128;
        __syncthreads();  // WAR on sA/sT + weight visibility on first iter
        for (int idx = tid; idx < 128 * DNG; idx += 512) {
            int e = idx >> 6, g = idx & 63;
            sA[g * 129 + e] = edge_attr[(size_t)(eg0 + e) * DNG + g];
        }
        if (tid < 128) {
            int e = eg0 + tid;
            sSrc[tid] = ei[e];
            sDst[tid] = ei[EEDGES + e];
            float L = elen[e];
            float cv = 0.5f * (__cosf(L * (FPI / 10.0f)) + 1.0f);
            sC[tid] = (L <= 10.0f && L >= 0.0f) ? cv : 0.0f;
        }
        __syncthreads();

        unsigned long long acc[4][4];
#pragma unroll
        for (int i = 0; i < 4; ++i)
#pragma unroll
            for (int p = 0; p < 4; ++p) acc[i][p] = 0ull;
        mm_tile2<129, 32>(sA, sW1, DNG, e0, c0, acc);  // T = A @ W1

        // ssp(T + b1), stored transposed for stage 2
#pragma unroll
        for (int p = 0; p < 4; ++p) {
            float bx = sB1[c0 + 2 * p], by = sB1[c0 + 2 * p + 1];
#pragma unroll
            for (int i = 0; i < 4; ++i) {
                float2 v = unpack2(acc[i][p]);
                sT[(c0 + 2 * p) * 129 + e0 + 32 * i] = ssp_f(v.x + bx);
                sT[(c0 + 2 * p + 1) * 129 + e0 + 32 * i] = ssp_f(v.y + by);
            }
        }
        __syncthreads();

#pragma unroll
        for (int i = 0; i < 4; ++i)
#pragma unroll
            for (int p = 0; p < 4; ++p) acc[i][p] = 0ull;
        mm_tile2<129, 32>(sT, sW2, DNF, e0, c0, acc);  // W = ssp(T) @ W2

        float bb2[8];
#pragma unroll
        for (int j = 0; j < 8; ++j) bb2[j] = sB2[c0 + j];

        // epilogue: msg = (W + b2) * C * h[src], scatter-add to agg[dst]
#pragma unroll
        for (int i = 0; i < 4; ++i) {
            int el = e0 + 32 * i;
            float cv = sC[el];
            if (cv != 0.0f) {
                int s = sSrc[el], d = sDst[el];
                const float* hp = g_h + (size_t)s * DNF + c0;
                float4 h0 = *(const float4*)hp;
                float4 h1 = *(const float4*)(hp + 4);
                float* dp = g_agg + (size_t)d * DNF + c0;
                float2 v0 = unpack2(acc[i][0]), v1 = unpack2(acc[i][1]);
                float2 v2 = unpack2(acc[i][2]), v3 = unpack2(acc[i][3]);
                red_add_v4(dp,
                           (v0.x + bb2[0]) * cv * h0.x,
                           (v0.y + bb2[1]) * cv * h0.y,
                           (v1.x + bb2[2]) * cv * h0.z,
                           (v1.y + bb2[3]) * cv * h0.w);
                red_add_v4(dp + 4,
                           (v2.x + bb2[4]) * cv * h1.x,
                           (v2.y + bb2[5]) * cv * h1.y,
                           (v3.x + bb2[6]) * cv * h1.z,
                           (v3.y + bb2[7]) * cv * h1.w);
            }
        }
    }
}

// -------- Kernel 3: out = ssp(agg@lin2_w + lin2_b) @ lin_w + lin_b (TE=64, 256 thr) -------
extern "C" __global__ void __launch_bounds__(256, 1)
k_out(const float* __restrict__ w2, const float* __restrict__ b2,
      const float* __restrict__ w3, const float* __restrict__ b3,
      float* __restrict__ out) {
    extern __shared__ float sm[];
    float* sW2 = sm;                // 128*128
    float* sW3 = sW2 + DNF * DHID;  // 128*128
    float* sA  = sW3 + DHID * DHID; // 128*65
    float* sT  = sA + DNF * 65;     // 128*65
    float* sB2 = sT + DHID * 65;    // 128
    float* sB3 = sB2 + DHID;        // 128

    const int tid = threadIdx.x;
    const int e0 = tid >> 4;        // 0..15
    const int c0 = (tid & 15) * 8;

    for (int i = tid; i < DNF * DHID / 4; i += 256)
        ((float4*)sW2)[i] = ((const float4*)w2)[i];
    for (int i = tid; i < DHID * DHID / 4; i += 256)
        ((float4*)sW3)[i] = ((const float4*)w3)[i];
    if (tid < DHID) { sB2[tid] = b2[tid]; sB3[tid] = b3[tid]; }

    const int ntiles = (NNODES + 63) / 64;
    for (int tile = blockIdx.x; tile < ntiles; tile += gridDim.x) {
        const int r0 = tile * 64;
        __syncthreads();
        for (int idx = tid; idx < 64 * DNF; idx += 256) {
            int e = idx >> 7, k = idx & 127;
            int r = r0 + e;
            sA[k * 65 + e] = (r < NNODES) ? g_agg[(size_t)r * DNF + k] : 0.0f;
        }
        __syncthreads();

        unsigned long long acc[4][4];
#pragma unroll
        for (int i = 0; i < 4; ++i)
#pragma unroll
            for (int p = 0; p < 4; ++p) acc[i][p] = 0ull;
        mm_tile2<65, 16>(sA, sW2, DNF, e0, c0, acc);

#pragma unroll
        for (int p = 0; p < 4; ++p) {
            float bx = sB2[c0 + 2 * p], by = sB2[c0 + 2 * p + 1];
#pragma unroll
            for (int i = 0; i < 4; ++i) {
                float2 v = unpack2(acc[i][p]);
                sT[(c0 + 2 * p) * 65 + e0 + 16 * i] = ssp_f(v.x + bx);
                sT[(c0 + 2 * p + 1) * 65 + e0 + 16 * i] = ssp_f(v.y + by);
            }
        }
        __syncthreads();

#pragma unroll
        for (int i = 0; i < 4; ++i)
#pragma unroll
            for (int p = 0; p < 4; ++p) acc[i][p] = 0ull;
        mm_tile2<65, 16>(sT, sW3, DHID, e0, c0, acc);

#pragma unroll
        for (int i = 0; i < 4; ++i) {
            int r = r0 + e0 + 16 * i;
            if (r < NNODES) {
                float2 v0 = unpack2(acc[i][0]), v1 = unpack2(acc[i][1]);
                float2 v2 = unpack2(acc[i][2]), v3 = unpack2(acc[i][3]);
                *(float4*)(out + (size_t)r * DHID + c0) =
                    make_float4(v0.x + sB3[c0 + 0], v0.y + sB3[c0 + 1],
                                v1.x + sB3[c0 + 2], v1.y + sB3[c0 + 3]);
                *(float4*)(out + (size_t)r * DHID + c0 + 4) =
                    make_float4(v2.x + sB3[c0 + 4], v2.y + sB3[c0 + 5],
                                v3.x + sB3[c0 + 6], v3.y + sB3[c0 + 7]);
            }
        }
    }
}

extern "C" void kernel_launch(void* const* d_in, const int* in_sizes, int n_in,
                              void* d_out, int out_size) {
    const float* x      = (const float*)d_in[0];
    const int*   ei     = (const int*)d_in[1];
    const float* elen   = (const float*)d_in[2];
    const float* eattr  = (const float*)d_in[3];
    const float* lin1_w = (const float*)d_in[4];
    const float* nn_w1  = (const float*)d_in[5];
    const float* nn_b1  = (const float*)d_in[6];
    const float* nn_w2  = (const float*)d_in[7];
    const float* nn_b2  = (const float*)d_in[8];
    const float* lin2_w = (const float*)d_in[9];
    const float* lin2_b = (const float*)d_in[10];
    const float* lin_w  = (const float*)d_in[11];
    const float* lin_b  = (const float*)d_in[12];
    float* out = (float*)d_out;

    size_t sm1 = (size_t)(DHID * DNF + DHID * 129) * 4;
    size_t sm2 = (size_t)(DNG * DNF + DNF * DNF + DNG * 129 + DNF * 129
                          + DNF + DNF + 128 + 128 + 128) * 4;
    size_t sm3 = (size_t)(DNF * DHID + DHID * DHID + DNF * 65 + DHID * 65
                          + DHID + DHID) * 4;

    cudaFuncSetAttribute(k_proj_zero, cudaFuncAttributeMaxDynamicSharedMemorySize, (int)sm1);
    cudaFuncSetAttribute(k_edge,      cudaFuncAttributeMaxDynamicSharedMemorySize, (int)sm2);
    cudaFuncSetAttribute(k_out,       cudaFuncAttributeMaxDynamicSharedMemorySize, (int)sm3);

    k_proj_zero<<<152, 512, sm1>>>(x, lin1_w);
    k_edge<<<152, 512, sm2>>>(eattr, ei, elen, nn_w1, nn_b1, nn_w2, nn_b2);
    k_out<<<152, 256, sm3>>>(lin2_w, lin2_b, lin_w, lin_b, out);
}

// round 4
// speedup vs baseline: 1.8275x; 1.6639x over previous
#include <cuda_runtime.h>
#include <cstdint>

#define NNODES 50000
#define EEDGES 1600000
#define DHID 128
#define DNF 128
#define DNG 64
#define LN2 0.69314718055994530942f
#define FPI 3.14159265358979323846f

typedef unsigned long long ull;

// Scratch (static device arrays: allocation-free per harness rules)
__device__ float g_h[(size_t)NNODES * DNF];    // x @ lin1_w
__device__ float g_agg[(size_t)NNODES * DNF];  // segment_sum accumulator
__device__ int   g_cnt;                        // compacted edge count
__device__ int   g_eid[EEDGES];                // compacted: original edge id
__device__ int   g_src[EEDGES];
__device__ int   g_dst[EEDGES];
__device__ float g_C[EEDGES];                  // cutoff envelope

// ---------------- helpers ----------------
__device__ __forceinline__ float ssp_f(float v) {
    return fmaxf(v, 0.0f) + __logf(1.0f + __expf(-fabsf(v))) - LN2;
}
__device__ __forceinline__ void red_add_v4(float* p, float a, float b, float c, float d) {
    asm volatile("red.global.add.v4.f32 [%0], {%1, %2, %3, %4};"
                 :: "l"(p), "f"(a), "f"(b), "f"(c), "f"(d) : "memory");
}
__device__ __forceinline__ ull pack2(float a) {
    ull r;
    asm("mov.b64 %0, {%1, %1};" : "=l"(r) : "f"(a));
    return r;
}
__device__ __forceinline__ float2 unpack2(ull v) {
    float2 f;
    asm("mov.b64 {%0, %1}, %2;" : "=f"(f.x), "=f"(f.y) : "l"(v));
    return f;
}
__device__ __forceinline__ void fma2(ull& d, ull a, ull b) {
    asm("fma.rn.f32x2 %0, %1, %2, %0;" : "+l"(d) : "l"(a), "l"(b));
}

// 8x8 microkernel: acc[j][c] = (out[2rg+32j][c0+c], out[2rg+32j+1][c0+c])
// As: [k][row] stride 130 (row-pairs 8B aligned), Bs: [k][col] stride 128.
// Lane map: cg = tid>>4 (c0=8cg), rg = tid&15 (rg2=2rg).
// Per warp-k crossbar: A 4xLDS.64 (128B contig, bcast) + B 2xLDS.128 (2-addr bcast) = 6 cyc.
template <int K>
__device__ __forceinline__ void mm8x8(const float* __restrict__ As,
                                      const float* __restrict__ Bs,
                                      int rg2, int c0, ull acc[4][8]) {
#pragma unroll 4
    for (int k = 0; k < K; ++k) {
        const float* ar = As + k * 130 + rg2;
        ull a0 = *(const ull*)(ar);
        ull a1 = *(const ull*)(ar + 32);
        ull a2 = *(const ull*)(ar + 64);
        ull a3 = *(const ull*)(ar + 96);
        const float* br = Bs + k * 128 + c0;
        float4 b0 = *(const float4*)br;
        float4 b1 = *(const float4*)(br + 4);
        ull bb[8] = {pack2(b0.x), pack2(b0.y), pack2(b0.z), pack2(b0.w),
                     pack2(b1.x), pack2(b1.y), pack2(b1.z), pack2(b1.w)};
#pragma unroll
        for (int c = 0; c < 8; ++c) {
            fma2(acc[0][c], a0, bb[c]);
            fma2(acc[1][c], a1, bb[c]);
            fma2(acc[2][c], a2, bb[c]);
            fma2(acc[3][c], a3, bb[c]);
        }
    }
}

__device__ __forceinline__ void zero_acc(ull acc[4][8]) {
#pragma unroll
    for (int j = 0; j < 4; ++j)
#pragma unroll
        for (int c = 0; c < 8; ++c) acc[j][c] = 0ull;
}

// ---------------- Kernel 0: compact edges with C != 0 ----------------
extern "C" __global__ void __launch_bounds__(256)
k_compact(const int* __restrict__ ei, const float* __restrict__ elen) {
    const int stride = gridDim.x * blockDim.x;
    const int i0 = blockIdx.x * blockDim.x + threadIdx.x;
    const int lane = threadIdx.x & 31;
    const int nit = (EEDGES + stride - 1) / stride;
    for (int it = 0; it < nit; ++it) {
        int i = i0 + it * stride;
        bool in = i < EEDGES;
        float L = in ? elen[i] : -1.0f;
        bool valid = in && (L <= 10.0f) && (L >= 0.0f);
        unsigned mask = __ballot_sync(0xffffffffu, valid);
        if (mask) {
            int leader = __ffs(mask) - 1;
            int base = 0;
            if (lane == leader) base = atomicAdd(&g_cnt, __popc(mask));
            base = __shfl_sync(0xffffffffu, base, leader);
            if (valid) {
                int pos = base + __popc(mask & ((1u << lane) - 1u));
                g_eid[pos] = i;
                g_src[pos] = ei[i];
                g_dst[pos] = ei[EEDGES + i];
                g_C[pos] = 0.5f * (__cosf(L * (FPI / 10.0f)) + 1.0f);
            }
        }
    }
}

// ---------------- Kernel 1: h = x @ lin1_w, zero g_agg + g_cnt ----------------
extern "C" __global__ void __launch_bounds__(256, 1)
k_proj_zero(const float* __restrict__ x, const float* __restrict__ w1) {
    extern __shared__ float sm[];
    float* sW = sm;                 // 128*128
    float* sX = sW + DHID * DNF;    // 128*130 transposed tile
    const int tid = threadIdx.x;
    const int cg = tid >> 4, rg = tid & 15;
    const int c0 = cg * 8, rg2 = rg * 2;

    if (blockIdx.x == 0 && tid == 0) g_cnt = 0;

    for (int i = tid; i < DHID * DNF / 4; i += 256)
        ((float4*)sW)[i] = ((const float4*)w1)[i];

    const int ntiles = (NNODES + 127) / 128;
    for (int tile = blockIdx.x; tile < ntiles; tile += gridDim.x) {
        const int r0 = tile * 128;
        __syncthreads();
        {
            int e = tid >> 1, k0 = (tid & 1) << 6;
            int r = r0 + e;
            if (r < NNODES) {
                const float4* s4 = (const float4*)(x + (size_t)r * DHID + k0);
#pragma unroll
                for (int i = 0; i < 16; ++i) {
                    float4 v = s4[i];
                    int k = k0 + 4 * i;
                    sX[(k + 0) * 130 + e] = v.x;
                    sX[(k + 1) * 130 + e] = v.y;
                    sX[(k + 2) * 130 + e] = v.z;
                    sX[(k + 3) * 130 + e] = v.w;
                }
            }
        }
        __syncthreads();
        ull acc[4][8];
        zero_acc(acc);
        mm8x8<DHID>(sX, sW, rg2, c0, acc);
#pragma unroll
        for (int j = 0; j < 4; ++j) {
            int r = r0 + rg2 + 32 * j;
            float2 v0 = unpack2(acc[j][0]), v1 = unpack2(acc[j][1]);
            float2 v2 = unpack2(acc[j][2]), v3 = unpack2(acc[j][3]);
            float2 v4 = unpack2(acc[j][4]), v5 = unpack2(acc[j][5]);
            float2 v6 = unpack2(acc[j][6]), v7 = unpack2(acc[j][7]);
            if (r < NNODES) {
                *(float4*)(g_h + (size_t)r * DNF + c0) = make_float4(v0.x, v1.x, v2.x, v3.x);
                *(float4*)(g_h + (size_t)r * DNF + c0 + 4) = make_float4(v4.x, v5.x, v6.x, v7.x);
                *(float4*)(g_agg + (size_t)r * DNF + c0) = make_float4(0.f, 0.f, 0.f, 0.f);
                *(float4*)(g_agg + (size_t)r * DNF + c0 + 4) = make_float4(0.f, 0.f, 0.f, 0.f);
            }
            if (r + 1 < NNODES) {
                *(float4*)(g_h + (size_t)(r + 1) * DNF + c0) = make_float4(v0.y, v1.y, v2.y, v3.y);
                *(float4*)(g_h + (size_t)(r + 1) * DNF + c0 + 4) = make_float4(v4.y, v5.y, v6.y, v7.y);
                *(float4*)(g_agg + (size_t)(r + 1) * DNF + c0) = make_float4(0.f, 0.f, 0.f, 0.f);
                *(float4*)(g_agg + (size_t)(r + 1) * DNF + c0 + 4) = make_float4(0.f, 0.f, 0.f, 0.f);
            }
        }
    }
}

// ---------------- Kernel 2: edge MLP + gather/scatter over compacted edges ----------------
extern "C" __global__ void __launch_bounds__(256, 1)
k_edge(const float* __restrict__ edge_attr,
       const float* __restrict__ w1, const float* __restrict__ b1,
       const float* __restrict__ w2, const float* __restrict__ b2) {
    extern __shared__ float sm[];
    float* sW1 = sm;                  // 64*128
    float* sW2 = sW1 + DNG * DNF;     // 128*128
    float* sA  = sW2 + DNF * DNF;     // 64*130
    float* sT  = sA + DNG * 130;      // 128*130
    float* sB1 = sT + DNF * 130;      // 128
    float* sB2 = sB1 + 128;           // 128
    float* sC  = sB2 + 128;           // 128
    int* sSrc  = (int*)(sC + 128);    // 128
    int* sDst  = sSrc + 128;          // 128

    const int tid = threadIdx.x;
    const int cg = tid >> 4, rg = tid & 15;
    const int c0 = cg * 8, rg2 = rg * 2;

    for (int i = tid; i < DNG * DNF / 4; i += 256)
        ((float4*)sW1)[i] = ((const float4*)w1)[i];
    for (int i = tid; i < DNF * DNF / 4; i += 256)
        ((float4*)sW2)[i] = ((const float4*)w2)[i];
    if (tid < DNF) { sB1[tid] = b1[tid]; sB2[tid] = b2[tid]; }

    const int cnt = g_cnt;
    const int ntiles = (cnt + 127) >> 7;
    for (int tile = blockIdx.x; tile < ntiles; tile += gridDim.x) {
        const int eg0 = tile << 7;
        __syncthreads();   // prev tile fully consumed (also weights on first iter)
        {
            int e = tid >> 1, g0 = (tid & 1) << 5;
            int gi = eg0 + e;
            int eid = (gi < cnt) ? g_eid[gi] : 0;
            const float4* s4 = (const float4*)(edge_attr + (size_t)eid * DNG + g0);
#pragma unroll
            for (int i = 0; i < 8; ++i) {
                float4 v = s4[i];
                int g = g0 + 4 * i;
                sA[(g + 0) * 130 + e] = v.x;
                sA[(g + 1) * 130 + e] = v.y;
                sA[(g + 2) * 130 + e] = v.z;
                sA[(g + 3) * 130 + e] = v.w;
            }
            if ((tid & 1) == 0) {
                if (gi < cnt) {
                    sC[e] = g_C[gi];
                    sSrc[e] = g_src[gi];
                    sDst[e] = g_dst[gi];
                } else {
                    sC[e] = 0.0f;
                }
            }
        }
        __syncthreads();

        ull acc[4][8];
        zero_acc(acc);
        mm8x8<DNG>(sA, sW1, rg2, c0, acc);   // T = A @ W1

        // ssp(T + b1) -> sT transposed (STS.64 row-pairs)
#pragma unroll
        for (int c = 0; c < 8; ++c) {
            float bv = sB1[c0 + c];
#pragma unroll
            for (int j = 0; j < 4; ++j) {
                float2 v = unpack2(acc[j][c]);
                *(float2*)(sT + (c0 + c) * 130 + rg2 + 32 * j) =
                    make_float2(ssp_f(v.x + bv), ssp_f(v.y + bv));
            }
        }
        __syncthreads();

        zero_acc(acc);
        mm8x8<DNF>(sT, sW2, rg2, c0, acc);   // Wmat = ssp(T) @ W2

        float bb0 = sB2[c0 + 0], bb1 = sB2[c0 + 1], bb2v = sB2[c0 + 2], bb3 = sB2[c0 + 3];
        float bb4 = sB2[c0 + 4], bb5 = sB2[c0 + 5], bb6 = sB2[c0 + 6], bb7 = sB2[c0 + 7];

#pragma unroll
        for (int j = 0; j < 4; ++j) {
            int r0 = rg2 + 32 * j;
            float2 v0 = unpack2(acc[j][0]), v1 = unpack2(acc[j][1]);
            float2 v2 = unpack2(acc[j][2]), v3 = unpack2(acc[j][3]);
            float2 v4 = unpack2(acc[j][4]), v5 = unpack2(acc[j][5]);
            float2 v6 = unpack2(acc[j][6]), v7 = unpack2(acc[j][7]);
            float cv0 = sC[r0], cv1 = sC[r0 + 1];
            if (cv0 != 0.0f) {
                const float* hp = g_h + (size_t)sSrc[r0] * DNF + c0;
                float4 h0 = *(const float4*)hp;
                float4 h1 = *(const float4*)(hp + 4);
                float* dp = g_agg + (size_t)sDst[r0] * DNF + c0;
                red_add_v4(dp, (v0.x + bb0) * cv0 * h0.x, (v1.x + bb1) * cv0 * h0.y,
                               (v2.x + bb2v) * cv0 * h0.z, (v3.x + bb3) * cv0 * h0.w);
                red_add_v4(dp + 4, (v4.x + bb4) * cv0 * h1.x, (v5.x + bb5) * cv0 * h1.y,
                                   (v6.x + bb6) * cv0 * h1.z, (v7.x + bb7) * cv0 * h1.w);
            }
            if (cv1 != 0.0f) {
                const float* hp = g_h + (size_t)sSrc[r0 + 1] * DNF + c0;
                float4 h0 = *(const float4*)hp;
                float4 h1 = *(const float4*)(hp + 4);
                float* dp = g_agg + (size_t)sDst[r0 + 1] * DNF + c0;
                red_add_v4(dp, (v0.y + bb0) * cv1 * h0.x, (v1.y + bb1) * cv1 * h0.y,
                               (v2.y + bb2v) * cv1 * h0.z, (v3.y + bb3) * cv1 * h0.w);
                red_add_v4(dp + 4, (v4.y + bb4) * cv1 * h1.x, (v5.y + bb5) * cv1 * h1.y,
                                   (v6.y + bb6) * cv1 * h1.z, (v7.y + bb7) * cv1 * h1.w);
            }
        }
    }
}

// -------- Kernel 3: out = ssp(agg@lin2_w + lin2_b) @ lin_w + lin_b --------
extern "C" __global__ void __launch_bounds__(256, 1)
k_out(const float* __restrict__ w2, const float* __restrict__ b2,
      const float* __restrict__ w3, const float* __restrict__ b3,
      float* __restrict__ out) {
    extern __shared__ float sm[];
    float* sW2 = sm;                  // 128*128 (lin2_w)
    float* sW3 = sW2 + DNF * DHID;    // 128*128 (lin_w)
    float* sA  = sW3 + DHID * DHID;   // 128*130 (aliased A then T)
    float* sB2 = sA + DNF * 130;      // 128
    float* sB3 = sB2 + 128;           // 128

    const int tid = threadIdx.x;
    const int cg = tid >> 4, rg = tid & 15;
    const int c0 = cg * 8, rg2 = rg * 2;

    for (int i = tid; i < DNF * DHID / 4; i += 256)
        ((float4*)sW2)[i] = ((const float4*)w2)[i];
    for (int i = tid; i < DHID * DHID / 4; i += 256)
        ((float4*)sW3)[i] = ((const float4*)w3)[i];
    if (tid < DHID) { sB2[tid] = b2[tid]; sB3[tid] = b3[tid]; }

    const int ntiles = (NNODES + 127) / 128;
    for (int tile = blockIdx.x; tile < ntiles; tile += gridDim.x) {
        const int r0 = tile * 128;
        __syncthreads();
        {
            int e = tid >> 1, k0 = (tid & 1) << 6;
            int r = r0 + e;
            const float4* s4 = (const float4*)(g_agg + (size_t)r * DNF + k0);
#pragma unroll
            for (int i = 0; i < 16; ++i) {
                float4 v = (r < NNODES) ? s4[i] : make_float4(0.f, 0.f, 0.f, 0.f);
                int k = k0 + 4 * i;
                sA[(k + 0) * 130 + e] = v.x;
                sA[(k + 1) * 130 + e] = v.y;
                sA[(k + 2) * 130 + e] = v.z;
                sA[(k + 3) * 130 + e] = v.w;
            }
        }
        __syncthreads();

        ull acc[4][8];
        zero_acc(acc);
        mm8x8<DNF>(sA, sW2, rg2, c0, acc);
        __syncthreads();   // everyone done reading sA before overwriting as T

        // ssp(mid + b2) -> sA (as transposed T)
#pragma unroll
        for (int c = 0; c < 8; ++c) {
            float bv = sB2[c0 + c];
#pragma unroll
            for (int j = 0; j < 4; ++j) {
                float2 v = unpack2(acc[j][c]);
                *(float2*)(sA + (c0 + c) * 130 + rg2 + 32 * j) =
                    make_float2(ssp_f(v.x + bv), ssp_f(v.y + bv));
            }
        }
        __syncthreads();

        zero_acc(acc);
        mm8x8<DHID>(sA, sW3, rg2, c0, acc);

#pragma unroll
        for (int j = 0; j < 4; ++j) {
            int r = r0 + rg2 + 32 * j;
            float2 v0 = unpack2(acc[j][0]), v1 = unpack2(acc[j][1]);
            float2 v2 = unpack2(acc[j][2]), v3 = unpack2(acc[j][3]);
            float2 v4 = unpack2(acc[j][4]), v5 = unpack2(acc[j][5]);
            float2 v6 = unpack2(acc[j][6]), v7 = unpack2(acc[j][7]);
            if (r < NNODES) {
                *(float4*)(out + (size_t)r * DHID + c0) =
                    make_float4(v0.x + sB3[c0 + 0], v1.x + sB3[c0 + 1],
                                v2.x + sB3[c0 + 2], v3.x + sB3[c0 + 3]);
                *(float4*)(out + (size_t)r * DHID + c0 + 4) =
                    make_float4(v4.x + sB3[c0 + 4], v5.x + sB3[c0 + 5],
                                v6.x + sB3[c0 + 6], v7.x + sB3[c0 + 7]);
            }
            if (r + 1 < NNODES) {
                *(float4*)(out + (size_t)(r + 1) * DHID + c0) =
                    make_float4(v0.y + sB3[c0 + 0], v1.y + sB3[c0 + 1],
                                v2.y + sB3[c0 + 2], v3.y + sB3[c0 + 3]);
                *(float4*)(out + (size_t)(r + 1) * DHID + c0 + 4) =
                    make_float4(v4.y + sB3[c0 + 4], v5.y + sB3[c0 + 5],
                                v6.y + sB3[c0 + 6], v7.y + sB3[c0 + 7]);
            }
        }
    }
}

extern "C" void kernel_launch(void* const* d_in, const int* in_sizes, int n_in,
                              void* d_out, int out_size) {
    const float* x      = (const float*)d_in[0];
    const int*   ei     = (const int*)d_in[1];
    const float* elen   = (const float*)d_in[2];
    const float* eattr  = (const float*)d_in[3];
    const float* lin1_w = (const float*)d_in[4];
    const float* nn_w1  = (const float*)d_in[5];
    const float* nn_b1  = (const float*)d_in[6];
    const float* nn_w2  = (const float*)d_in[7];
    const float* nn_b2  = (const float*)d_in[8];
    const float* lin2_w = (const float*)d_in[9];
    const float* lin2_b = (const float*)d_in[10];
    const float* lin_w  = (const float*)d_in[11];
    const float* lin_b  = (const float*)d_in[12];
    float* out = (float*)d_out;

    size_t sm1 = (size_t)(DHID * DNF + DHID * 130) * 4;
    size_t sm2 = (size_t)(DNG * DNF + DNF * DNF + DNG * 130 + DNF * 130 + 5 * 128) * 4;
    size_t sm3 = (size_t)(DNF * DHID + DHID * DHID + DNF * 130 + 2 * 128) * 4;

    cudaFuncSetAttribute(k_proj_zero, cudaFuncAttributeMaxDynamicSharedMemorySize, (int)sm1);
    cudaFuncSetAttribute(k_edge, cudaFuncAttributeMaxDynamicSharedMemorySize, (int)sm2);
    cudaFuncSetAttribute(k_out, cudaFuncAttributeMaxDynamicSharedMemorySize, (int)sm3);

    k_proj_zero<<<152, 256, sm1>>>(x, lin1_w);          // also zeroes g_cnt + g_agg
    k_compact<<<152, 256>>>(ei, elen);
    k_edge<<<152, 256, sm2>>>(eattr, nn_w1, nn_b1, nn_w2, nn_b2);
    k_out<<<152, 256, sm3>>>(lin2_w, lin2_b, lin_w, lin_b, out);
}

// round 5
// speedup vs baseline: 1.8799x; 1.0286x over previous
#include <cuda_runtime.h>
#include <cstdint>

#define NNODES 50000
#define EEDGES 1600000
#define DHID 128
#define DNF 128
#define DNG 64
#define LN2 0.69314718055994530942f
#define FPI 3.14159265358979323846f

typedef unsigned long long ull;

// Scratch (static device arrays: allocation-free per harness rules)
__device__ float g_h[(size_t)NNODES * DNF];    // x @ lin1_w
__device__ float g_agg[(size_t)NNODES * DNF];  // segment_sum accumulator
__device__ int   g_cnt;                        // compacted edge count
__device__ int   g_eid[EEDGES];                // compacted: original edge id
__device__ int   g_src[EEDGES];
__device__ int   g_dst[EEDGES];
__device__ float g_C[EEDGES];                  // cutoff envelope

// ---------------- helpers ----------------
__device__ __forceinline__ float ssp_f(float v) {
    return fmaxf(v, 0.0f) + __logf(1.0f + __expf(-fabsf(v))) - LN2;
}
__device__ __forceinline__ void red_add_v4(float* p, float a, float b, float c, float d) {
    asm volatile("red.global.add.v4.f32 [%0], {%1, %2, %3, %4};"
                 :: "l"(p), "f"(a), "f"(b), "f"(c), "f"(d) : "memory");
}
__device__ __forceinline__ ull pack2(float a) {
    ull r;
    asm("mov.b64 %0, {%1, %1};" : "=l"(r) : "f"(a));
    return r;
}
__device__ __forceinline__ float2 unpack2(ull v) {
    float2 f;
    asm("mov.b64 {%0, %1}, %2;" : "=f"(f.x), "=f"(f.y) : "l"(v));
    return f;
}
__device__ __forceinline__ void fma2(ull& d, ull a, ull b) {
    asm("fma.rn.f32x2 %0, %1, %2, %0;" : "+l"(d) : "l"(a), "l"(b));
}

// 4x8 microkernel, 512 threads covering a 128x128 output tile.
// Lane map: rg = tid&31 (rows rg, rg+32, rg+64, rg+96), cg = tid>>5 (cols 8cg..8cg+7).
// acc[j][p] = (out[rg+32j][c0+2p], out[rg+32j][c0+2p+1])  -- f32x2 column pairs.
// As: [k][row] stride 130; Bs: [k][col] stride 128.
// Per warp-k: 4x LDS.32 (128B contig bcast) + 2x LDS.128 (bcast) + 4 pack movs + 16 FFMA2.
template <int K>
__device__ __forceinline__ void mm4x8(const float* __restrict__ As,
                                      const float* __restrict__ Bs,
                                      int rg, int c0, ull acc[4][4]) {
#pragma unroll 4
    for (int k = 0; k < K; ++k) {
        const float* ar = As + k * 130 + rg;
        ull a0 = pack2(ar[0]);
        ull a1 = pack2(ar[32]);
        ull a2 = pack2(ar[64]);
        ull a3 = pack2(ar[96]);
        const float* br = Bs + k * 128 + c0;
        ulonglong2 b01 = *(const ulonglong2*)br;          // cols c0..c0+3 (32B aligned)
        ulonglong2 b23 = *(const ulonglong2*)(br + 4);    // cols c0+4..c0+7
        ull bb[4] = {b01.x, b01.y, b23.x, b23.y};
#pragma unroll
        for (int p = 0; p < 4; ++p) {
            fma2(acc[0][p], a0, bb[p]);
            fma2(acc[1][p], a1, bb[p]);
            fma2(acc[2][p], a2, bb[p]);
            fma2(acc[3][p], a3, bb[p]);
        }
    }
}

__device__ __forceinline__ void zero_acc(ull acc[4][4]) {
#pragma unroll
    for (int j = 0; j < 4; ++j)
#pragma unroll
        for (int p = 0; p < 4; ++p) acc[j][p] = 0ull;
}

// ---------------- Kernel 0: compact edges with C != 0 ----------------
extern "C" __global__ void __launch_bounds__(256)
k_compact(const int* __restrict__ ei, const float* __restrict__ elen) {
    const int stride = gridDim.x * blockDim.x;
    const int i0 = blockIdx.x * blockDim.x + threadIdx.x;
    const int lane = threadIdx.x & 31;
    const int nit = (EEDGES + stride - 1) / stride;
    for (int it = 0; it < nit; ++it) {
        int i = i0 + it * stride;
        bool in = i < EEDGES;
        float L = in ? elen[i] : -1.0f;
        bool valid = in && (L <= 10.0f) && (L >= 0.0f);
        unsigned mask = __ballot_sync(0xffffffffu, valid);
        if (mask) {
            int leader = __ffs(mask) - 1;
            int base = 0;
            if (lane == leader) base = atomicAdd(&g_cnt, __popc(mask));
            base = __shfl_sync(0xffffffffu, base, leader);
            if (valid) {
                int pos = base + __popc(mask & ((1u << lane) - 1u));
                g_eid[pos] = i;
                g_src[pos] = ei[i];
                g_dst[pos] = ei[EEDGES + i];
                g_C[pos] = 0.5f * (__cosf(L * (FPI / 10.0f)) + 1.0f);
            }
        }
    }
}

// ---------------- Kernel 1: h = x @ lin1_w, zero g_agg + g_cnt ----------------
extern "C" __global__ void __launch_bounds__(512, 1)
k_proj_zero(const float* __restrict__ x, const float* __restrict__ w1) {
    extern __shared__ float sm[];
    float* sW = sm;                 // 128*128
    float* sX = sW + DHID * DNF;    // 128*130 transposed tile
    const int tid = threadIdx.x;
    const int rg = tid & 31, cg = tid >> 5;
    const int c0 = cg * 8;

    if (blockIdx.x == 0 && tid == 0) g_cnt = 0;

    for (int i = tid; i < DHID * DNF / 4; i += 512)
        ((float4*)sW)[i] = ((const float4*)w1)[i];

    const int ntiles = (NNODES + 127) / 128;
    for (int tile = blockIdx.x; tile < ntiles; tile += gridDim.x) {
        const int r0 = tile * 128;
        __syncthreads();
        {
            int e = tid >> 2, k0 = (tid & 3) << 5;
            int r = r0 + e;
            if (r < NNODES) {
                const float4* s4 = (const float4*)(x + (size_t)r * DHID + k0);
#pragma unroll
                for (int i = 0; i < 8; ++i) {
                    float4 v = s4[i];
                    int k = k0 + 4 * i;
                    sX[(k + 0) * 130 + e] = v.x;
                    sX[(k + 1) * 130 + e] = v.y;
                    sX[(k + 2) * 130 + e] = v.z;
                    sX[(k + 3) * 130 + e] = v.w;
                }
            }
        }
        __syncthreads();
        ull acc[4][4];
        zero_acc(acc);
        mm4x8<DHID>(sX, sW, rg, c0, acc);
#pragma unroll
        for (int j = 0; j < 4; ++j) {
            int r = r0 + rg + 32 * j;
            if (r < NNODES) {
                float2 v0 = unpack2(acc[j][0]), v1 = unpack2(acc[j][1]);
                float2 v2 = unpack2(acc[j][2]), v3 = unpack2(acc[j][3]);
                *(float4*)(g_h + (size_t)r * DNF + c0) = make_float4(v0.x, v0.y, v1.x, v1.y);
                *(float4*)(g_h + (size_t)r * DNF + c0 + 4) = make_float4(v2.x, v2.y, v3.x, v3.y);
                *(float4*)(g_agg + (size_t)r * DNF + c0) = make_float4(0.f, 0.f, 0.f, 0.f);
                *(float4*)(g_agg + (size_t)r * DNF + c0 + 4) = make_float4(0.f, 0.f, 0.f, 0.f);
            }
        }
    }
}

// ---------------- Kernel 2: edge MLP + gather/scatter over compacted edges ----------------
extern "C" __global__ void __launch_bounds__(512, 1)
k_edge(const float* __restrict__ edge_attr,
       const float* __restrict__ w1, const float* __restrict__ b1,
       const float* __restrict__ w2, const float* __restrict__ b2) {
    extern __shared__ float sm[];
    float* sW1 = sm;                  // 64*128
    float* sW2 = sW1 + DNG * DNF;     // 128*128
    float* sA  = sW2 + DNF * DNF;     // 64*130
    float* sT  = sA + DNG * 130;      // 128*130
    float* sB1 = sT + DNF * 130;      // 128
    float* sB2 = sB1 + 128;           // 128
    float* sC  = sB2 + 128;           // 128
    int* sSrc  = (int*)(sC + 128);    // 128
    int* sDst  = sSrc + 128;          // 128

    const int tid = threadIdx.x;
    const int rg = tid & 31, cg = tid >> 5;
    const int c0 = cg * 8;

    for (int i = tid; i < DNG * DNF / 4; i += 512)
        ((float4*)sW1)[i] = ((const float4*)w1)[i];
    for (int i = tid; i < DNF * DNF / 4; i += 512)
        ((float4*)sW2)[i] = ((const float4*)w2)[i];
    if (tid < DNF) { sB1[tid] = b1[tid]; sB2[tid] = b2[tid]; }

    const int cnt = g_cnt;
    const int ntiles = (cnt + 127) >> 7;
    for (int tile = blockIdx.x; tile < ntiles; tile += gridDim.x) {
        const int eg0 = tile << 7;
        __syncthreads();   // prev tile fully consumed (also weights on first iter)
        {
            int e = tid >> 2, g0 = (tid & 3) << 4;
            int gi = eg0 + e;
            int eid = (gi < cnt) ? g_eid[gi] : 0;
            const float4* s4 = (const float4*)(edge_attr + (size_t)eid * DNG + g0);
#pragma unroll
            for (int i = 0; i < 4; ++i) {
                float4 v = s4[i];
                int g = g0 + 4 * i;
                sA[(g + 0) * 130 + e] = v.x;
                sA[(g + 1) * 130 + e] = v.y;
                sA[(g + 2) * 130 + e] = v.z;
                sA[(g + 3) * 130 + e] = v.w;
            }
            if ((tid & 3) == 0) {
                if (gi < cnt) {
                    sC[e] = g_C[gi];
                    sSrc[e] = g_src[gi];
                    sDst[e] = g_dst[gi];
                } else {
                    sC[e] = 0.0f;
                }
            }
        }
        __syncthreads();

        ull acc[4][4];
        zero_acc(acc);
        mm4x8<DNG>(sA, sW1, rg, c0, acc);   // T = A @ W1

        // ssp(T + b1) -> sT transposed
#pragma unroll
        for (int p = 0; p < 4; ++p) {
            float bx = sB1[c0 + 2 * p], by = sB1[c0 + 2 * p + 1];
#pragma unroll
            for (int j = 0; j < 4; ++j) {
                float2 v = unpack2(acc[j][p]);
                int row = rg + 32 * j;
                sT[(c0 + 2 * p) * 130 + row] = ssp_f(v.x + bx);
                sT[(c0 + 2 * p + 1) * 130 + row] = ssp_f(v.y + by);
            }
        }
        __syncthreads();

        zero_acc(acc);
        mm4x8<DNF>(sT, sW2, rg, c0, acc);   // Wmat = ssp(T) @ W2

        float bb0 = sB2[c0 + 0], bb1 = sB2[c0 + 1], bb2v = sB2[c0 + 2], bb3 = sB2[c0 + 3];
        float bb4 = sB2[c0 + 4], bb5 = sB2[c0 + 5], bb6 = sB2[c0 + 6], bb7 = sB2[c0 + 7];

#pragma unroll
        for (int j = 0; j < 4; ++j) {
            int el = rg + 32 * j;
            float cv = sC[el];
            if (cv != 0.0f) {
                float2 v0 = unpack2(acc[j][0]), v1 = unpack2(acc[j][1]);
                float2 v2 = unpack2(acc[j][2]), v3 = unpack2(acc[j][3]);
                const float* hp = g_h + (size_t)sSrc[el] * DNF + c0;
                float4 h0 = *(const float4*)hp;
                float4 h1 = *(const float4*)(hp + 4);
                float* dp = g_agg + (size_t)sDst[el] * DNF + c0;
                red_add_v4(dp, (v0.x + bb0) * cv * h0.x, (v0.y + bb1) * cv * h0.y,
                               (v1.x + bb2v) * cv * h0.z, (v1.y + bb3) * cv * h0.w);
                red_add_v4(dp + 4, (v2.x + bb4) * cv * h1.x, (v2.y + bb5) * cv * h1.y,
                                   (v3.x + bb6) * cv * h1.z, (v3.y + bb7) * cv * h1.w);
            }
        }
    }
}

// -------- Kernel 3: out = ssp(agg@lin2_w + lin2_b) @ lin_w + lin_b --------
extern "C" __global__ void __launch_bounds__(512, 1)
k_out(const float* __restrict__ w2, const float* __restrict__ b2,
      const float* __restrict__ w3, const float* __restrict__ b3,
      float* __restrict__ out) {
    extern __shared__ float sm[];
    float* sW2 = sm;                  // 128*128 (lin2_w)
    float* sW3 = sW2 + DNF * DHID;    // 128*128 (lin_w)
    float* sA  = sW3 + DHID * DHID;   // 128*130 (aliased A then T)
    float* sB2 = sA + DNF * 130;      // 128
    float* sB3 = sB2 + 128;           // 128

    const int tid = threadIdx.x;
    const int rg = tid & 31, cg = tid >> 5;
    const int c0 = cg * 8;

    for (int i = tid; i < DNF * DHID / 4; i += 512)
        ((float4*)sW2)[i] = ((const float4*)w2)[i];
    for (int i = tid; i < DHID * DHID / 4; i += 512)
        ((float4*)sW3)[i] = ((const float4*)w3)[i];
    if (tid < DHID) { sB2[tid] = b2[tid]; sB3[tid] = b3[tid]; }

    const int ntiles = (NNODES + 127) / 128;
    for (int tile = blockIdx.x; tile < ntiles; tile += gridDim.x) {
        const int r0 = tile * 128;
        __syncthreads();
        {
            int e = tid >> 2, k0 = (tid & 3) << 5;
            int r = r0 + e;
            const float4* s4 = (const float4*)(g_agg + (size_t)r * DNF + k0);
#pragma unroll
            for (int i = 0; i < 8; ++i) {
                float4 v = (r < NNODES) ? s4[i] : make_float4(0.f, 0.f, 0.f, 0.f);
                int k = k0 + 4 * i;
                sA[(k + 0) * 130 + e] = v.x;
                sA[(k + 1) * 130 + e] = v.y;
                sA[(k + 2) * 130 + e] = v.z;
                sA[(k + 3) * 130 + e] = v.w;
            }
        }
        __syncthreads();

        ull acc[4][4];
        zero_acc(acc);
        mm4x8<DNF>(sA, sW2, rg, c0, acc);
        __syncthreads();   // all reads of sA done before overwrite as T

        // ssp(mid + b2) -> sA (as transposed T)
#pragma unroll
        for (int p = 0; p < 4; ++p) {
            float bx = sB2[c0 + 2 * p], by = sB2[c0 + 2 * p + 1];
#pragma unroll
            for (int j = 0; j < 4; ++j) {
                float2 v = unpack2(acc[j][p]);
                int row = rg + 32 * j;
                sA[(c0 + 2 * p) * 130 + row] = ssp_f(v.x + bx);
                sA[(c0 + 2 * p + 1) * 130 + row] = ssp_f(v.y + by);
            }
        }
        __syncthreads();

        zero_acc(acc);
        mm4x8<DHID>(sA, sW3, rg, c0, acc);

#pragma unroll
        for (int j = 0; j < 4; ++j) {
            int r = r0 + rg + 32 * j;
            if (r < NNODES) {
                float2 v0 = unpack2(acc[j][0]), v1 = unpack2(acc[j][1]);
                float2 v2 = unpack2(acc[j][2]), v3 = unpack2(acc[j][3]);
                *(float4*)(out + (size_t)r * DHID + c0) =
                    make_float4(v0.x + sB3[c0 + 0], v0.y + sB3[c0 + 1],
                                v1.x + sB3[c0 + 2], v1.y + sB3[c0 + 3]);
                *(float4*)(out + (size_t)r * DHID + c0 + 4) =
                    make_float4(v2.x + sB3[c0 + 4], v2.y + sB3[c0 + 5],
                                v3.x + sB3[c0 + 6], v3.y + sB3[c0 + 7]);
            }
        }
    }
}

extern "C" void kernel_launch(void* const* d_in, const int* in_sizes, int n_in,
                              void* d_out, int out_size) {
    const float* x      = (const float*)d_in[0];
    const int*   ei     = (const int*)d_in[1];
    const float* elen   = (const float*)d_in[2];
    const float* eattr  = (const float*)d_in[3];
    const float* lin1_w = (const float*)d_in[4];
    const float* nn_w1  = (const float*)d_in[5];
    const float* nn_b1  = (const float*)d_in[6];
    const float* nn_w2  = (const float*)d_in[7];
    const float* nn_b2  = (const float*)d_in[8];
    const float* lin2_w = (const float*)d_in[9];
    const float* lin2_b = (const float*)d_in[10];
    const float* lin_w  = (const float*)d_in[11];
    const float* lin_b  = (const float*)d_in[12];
    float* out = (float*)d_out;

    size_t sm1 = (size_t)(DHID * DNF + DHID * 130) * 4;
    size_t sm2 = (size_t)(DNG * DNF + DNF * DNF + DNG * 130 + DNF * 130 + 5 * 128) * 4;
    size_t sm3 = (size_t)(DNF * DHID + DHID * DHID + DNF * 130 + 2 * 128) * 4;

    cudaFuncSetAttribute(k_proj_zero, cudaFuncAttributeMaxDynamicSharedMemorySize, (int)sm1);
    cudaFuncSetAttribute(k_edge, cudaFuncAttributeMaxDynamicSharedMemorySize, (int)sm2);
    cudaFuncSetAttribute(k_out, cudaFuncAttributeMaxDynamicSharedMemorySize, (int)sm3);

    k_proj_zero<<<152, 512, sm1>>>(x, lin1_w);          // also zeroes g_cnt + g_agg
    k_compact<<<152, 256>>>(ei, elen);
    k_edge<<<152, 512, sm2>>>(eattr, nn_w1, nn_b1, nn_w2, nn_b2);
    k_out<<<152, 512, sm3>>>(lin2_w, lin2_b, lin_w, lin_b, out);
}

// round 6
// speedup vs baseline: 1.9652x; 1.0454x over previous
#include <cuda_runtime.h>
#include <cstdint>

#define NNODES 50000
#define EEDGES 1600000
#define DHID 128
#define DNF 128
#define DNG 64
#define LN2 0.69314718055994530942f
#define FPI 3.14159265358979323846f

typedef unsigned long long ull;

// Scratch (static device arrays: allocation-free per harness rules)
__device__ float g_h[(size_t)NNODES * DNF];    // x @ lin1_w
__device__ float g_agg[(size_t)NNODES * DNF];  // segment_sum accumulator
__device__ int   g_cnt;                        // compacted edge count
__device__ int   g_eid[EEDGES];                // compacted: original edge id
__device__ int   g_src[EEDGES];
__device__ int   g_dst[EEDGES];
__device__ float g_C[EEDGES];                  // cutoff envelope

// ---------------- helpers ----------------
__device__ __forceinline__ float ssp_f(float v) {
    return fmaxf(v, 0.0f) + __logf(1.0f + __expf(-fabsf(v))) - LN2;
}
__device__ __forceinline__ void red_add_v4(float* p, float a, float b, float c, float d) {
    asm volatile("red.global.add.v4.f32 [%0], {%1, %2, %3, %4};"
                 :: "l"(p), "f"(a), "f"(b), "f"(c), "f"(d) : "memory");
}
__device__ __forceinline__ ull pack2(float a) {
    ull r;
    asm("mov.b64 %0, {%1, %1};" : "=l"(r) : "f"(a));
    return r;
}
__device__ __forceinline__ float2 unpack2(ull v) {
    float2 f;
    asm("mov.b64 {%0, %1}, %2;" : "=f"(f.x), "=f"(f.y) : "l"(v));
    return f;
}
__device__ __forceinline__ void fma2(ull& d, ull a, ull b) {
    asm("fma.rn.f32x2 %0, %1, %2, %0;" : "+l"(d) : "l"(a), "l"(b));
}
__device__ __forceinline__ float4 ldcs4(const float* p) {
    float4 v;
    asm volatile("ld.global.cs.v4.f32 {%0,%1,%2,%3}, [%4];"
                 : "=f"(v.x), "=f"(v.y), "=f"(v.z), "=f"(v.w) : "l"(p));
    return v;
}
__device__ __forceinline__ float4 ldcg4(const float* p) {
    float4 v;
    asm volatile("ld.global.cg.v4.f32 {%0,%1,%2,%3}, [%4];"
                 : "=f"(v.x), "=f"(v.y), "=f"(v.z), "=f"(v.w) : "l"(p));
    return v;
}

// 8x8 microkernel, 256 threads covering a 128x128 tile, B streamed from GLOBAL (L1).
// Lane map: cg = tid>>4 (c0 = 8cg), rg = tid&15 (row pairs rg2=2rg, +32, +64, +96).
// acc[j][c] = (out[rg2+32j][c0+c], out[rg2+32j+1][c0+c])  -- f32x2 row pairs.
// As: [k][row] stride 130 (8B-aligned pairs). Bg: [k][col] stride 128 (row-major weights).
// Per warp-k: 4x LDS.64 (128B, half-warp bcast) + 2x LDG.128 (2-addr, 2 sectors)
//             + 8 pack movs + 32 FFMA2  -> 46 issues / 64 FMA-cyc.
template <int K>
__device__ __forceinline__ void mm8x8g(const float* __restrict__ As,
                                       const float* __restrict__ Bg,
                                       int rg2, int c0, ull acc[4][8]) {
#pragma unroll 4
    for (int k = 0; k < K; ++k) {
        const float* ar = As + k * 130 + rg2;
        ull a0 = *(const ull*)(ar);
        ull a1 = *(const ull*)(ar + 32);
        ull a2 = *(const ull*)(ar + 64);
        ull a3 = *(const ull*)(ar + 96);
        const float4* bp = (const float4*)(Bg + k * 128 + c0);
        float4 b0 = __ldg(bp);
        float4 b1 = __ldg(bp + 1);
        ull bb[8] = {pack2(b0.x), pack2(b0.y), pack2(b0.z), pack2(b0.w),
                     pack2(b1.x), pack2(b1.y), pack2(b1.z), pack2(b1.w)};
#pragma unroll
        for (int c = 0; c < 8; ++c) {
            fma2(acc[0][c], a0, bb[c]);
            fma2(acc[1][c], a1, bb[c]);
            fma2(acc[2][c], a2, bb[c]);
            fma2(acc[3][c], a3, bb[c]);
        }
    }
}

__device__ __forceinline__ void zero_acc(ull acc[4][8]) {
#pragma unroll
    for (int j = 0; j < 4; ++j)
#pragma unroll
        for (int c = 0; c < 8; ++c) acc[j][c] = 0ull;
}

// ---------------- Kernel 0: compact edges with C != 0 ----------------
extern "C" __global__ void __launch_bounds__(256)
k_compact(const int* __restrict__ ei, const float* __restrict__ elen) {
    const int stride = gridDim.x * blockDim.x;
    const int i0 = blockIdx.x * blockDim.x + threadIdx.x;
    const int lane = threadIdx.x & 31;
    const int nit = (EEDGES + stride - 1) / stride;
    for (int it = 0; it < nit; ++it) {
        int i = i0 + it * stride;
        bool in = i < EEDGES;
        float L = in ? elen[i] : -1.0f;
        bool valid = in && (L <= 10.0f) && (L >= 0.0f);
        unsigned mask = __ballot_sync(0xffffffffu, valid);
        if (mask) {
            int leader = __ffs(mask) - 1;
            int base = 0;
            if (lane == leader) base = atomicAdd(&g_cnt, __popc(mask));
            base = __shfl_sync(0xffffffffu, base, leader);
            if (valid) {
                int pos = base + __popc(mask & ((1u << lane) - 1u));
                g_eid[pos] = i;
                g_src[pos] = ei[i];
                g_dst[pos] = ei[EEDGES + i];
                g_C[pos] = 0.5f * (__cosf(L * (FPI / 10.0f)) + 1.0f);
            }
        }
    }
}

// ---------------- Kernel 1: h = x @ lin1_w, zero g_agg + g_cnt ----------------
extern "C" __global__ void __launch_bounds__(256, 2)
k_proj_zero(const float* __restrict__ x, const float* __restrict__ w1) {
    extern __shared__ float sm[];
    float* sX = sm;                 // 128*130 transposed tile
    const int tid = threadIdx.x;
    const int cg = tid >> 4, rg = tid & 15;
    const int c0 = cg * 8, rg2 = rg * 2;

    if (blockIdx.x == 0 && tid == 0) g_cnt = 0;

    const int ntiles = (NNODES + 127) / 128;
    for (int tile = blockIdx.x; tile < ntiles; tile += gridDim.x) {
        const int r0 = tile * 128;
        __syncthreads();
        {
            int e = tid >> 1, k0 = (tid & 1) << 6;
            int r = r0 + e;
            if (r < NNODES) {
                const float* src = x + (size_t)r * DHID + k0;
#pragma unroll
                for (int i = 0; i < 16; ++i) {
                    float4 v = ldcs4(src + 4 * i);
                    int k = k0 + 4 * i;
                    sX[(k + 0) * 130 + e] = v.x;
                    sX[(k + 1) * 130 + e] = v.y;
                    sX[(k + 2) * 130 + e] = v.z;
                    sX[(k + 3) * 130 + e] = v.w;
                }
            }
        }
        __syncthreads();
        ull acc[4][8];
        zero_acc(acc);
        mm8x8g<DHID>(sX, w1, rg2, c0, acc);
#pragma unroll
        for (int j = 0; j < 4; ++j) {
            int r = r0 + rg2 + 32 * j;
            float2 v0 = unpack2(acc[j][0]), v1 = unpack2(acc[j][1]);
            float2 v2 = unpack2(acc[j][2]), v3 = unpack2(acc[j][3]);
            float2 v4 = unpack2(acc[j][4]), v5 = unpack2(acc[j][5]);
            float2 v6 = unpack2(acc[j][6]), v7 = unpack2(acc[j][7]);
            if (r < NNODES) {
                *(float4*)(g_h + (size_t)r * DNF + c0) = make_float4(v0.x, v1.x, v2.x, v3.x);
                *(float4*)(g_h + (size_t)r * DNF + c0 + 4) = make_float4(v4.x, v5.x, v6.x, v7.x);
                *(float4*)(g_agg + (size_t)r * DNF + c0) = make_float4(0.f, 0.f, 0.f, 0.f);
                *(float4*)(g_agg + (size_t)r * DNF + c0 + 4) = make_float4(0.f, 0.f, 0.f, 0.f);
            }
            if (r + 1 < NNODES) {
                *(float4*)(g_h + (size_t)(r + 1) * DNF + c0) = make_float4(v0.y, v1.y, v2.y, v3.y);
                *(float4*)(g_h + (size_t)(r + 1) * DNF + c0 + 4) = make_float4(v4.y, v5.y, v6.y, v7.y);
                *(float4*)(g_agg + (size_t)(r + 1) * DNF + c0) = make_float4(0.f, 0.f, 0.f, 0.f);
                *(float4*)(g_agg + (size_t)(r + 1) * DNF + c0 + 4) = make_float4(0.f, 0.f, 0.f, 0.f);
            }
        }
    }
}

// ---------------- Kernel 2: edge MLP + gather/scatter over compacted edges ----------------
// smem: sTile (union: sA 64x130 rows / sT 128x130 rows) + meta. Weights via L1.
extern "C" __global__ void __launch_bounds__(256, 2)
k_edge(const float* __restrict__ edge_attr,
       const float* __restrict__ w1, const float* __restrict__ b1,
       const float* __restrict__ w2, const float* __restrict__ b2) {
    extern __shared__ float sm[];
    float* sTile = sm;                     // 128*130 (sA aliases first 64 rows)
    float* sC  = sTile + DNF * 130;        // 128
    int* sSrc  = (int*)(sC + 128);         // 128
    int* sDst  = sSrc + 128;               // 128

    const int tid = threadIdx.x;
    const int cg = tid >> 4, rg = tid & 15;
    const int c0 = cg * 8, rg2 = rg * 2;

    const int cnt = g_cnt;
    const int ntiles = (cnt + 127) >> 7;
    for (int tile = blockIdx.x; tile < ntiles; tile += gridDim.x) {
        const int eg0 = tile << 7;
        __syncthreads();   // prev tile epilogue done with sC/sSrc/sDst, GEMM2 done with sT
        {
            int e = tid >> 1, g0 = (tid & 1) << 5;
            int gi = eg0 + e;
            int eid = (gi < cnt) ? g_eid[gi] : 0;
            const float* src = edge_attr + (size_t)eid * DNG + g0;
#pragma unroll
            for (int i = 0; i < 8; ++i) {
                float4 v = ldcs4(src + 4 * i);
                int g = g0 + 4 * i;
                sTile[(g + 0) * 130 + e] = v.x;
                sTile[(g + 1) * 130 + e] = v.y;
                sTile[(g + 2) * 130 + e] = v.z;
                sTile[(g + 3) * 130 + e] = v.w;
            }
            if ((tid & 1) == 0) {
                if (gi < cnt) {
                    sC[e] = g_C[gi];
                    sSrc[e] = g_src[gi];
                    sDst[e] = g_dst[gi];
                } else {
                    sC[e] = 0.0f;
                }
            }
        }
        __syncthreads();

        ull acc[4][8];
        zero_acc(acc);
        mm8x8g<DNG>(sTile, w1, rg2, c0, acc);   // T = A @ W1
        __syncthreads();   // all reads of sA done before overwriting as sT

        // ssp(T + b1) -> sT transposed (STS.64 row-pairs)
        {
            float4 bA = __ldg((const float4*)(b1 + c0));
            float4 bB = __ldg((const float4*)(b1 + c0 + 4));
            float bv[8] = {bA.x, bA.y, bA.z, bA.w, bB.x, bB.y, bB.z, bB.w};
#pragma unroll
            for (int c = 0; c < 8; ++c) {
#pragma unroll
                for (int j = 0; j < 4; ++j) {
                    float2 v = unpack2(acc[j][c]);
                    *(float2*)(sTile + (c0 + c) * 130 + rg2 + 32 * j) =
                        make_float2(ssp_f(v.x + bv[c]), ssp_f(v.y + bv[c]));
                }
            }
        }
        __syncthreads();

        zero_acc(acc);
        mm8x8g<DNF>(sTile, w2, rg2, c0, acc);   // Wmat = ssp(T) @ W2

        float4 bA = __ldg((const float4*)(b2 + c0));
        float4 bB = __ldg((const float4*)(b2 + c0 + 4));

#pragma unroll
        for (int j = 0; j < 4; ++j) {
            int r0 = rg2 + 32 * j;
            float2 v0 = unpack2(acc[j][0]), v1 = unpack2(acc[j][1]);
            float2 v2 = unpack2(acc[j][2]), v3 = unpack2(acc[j][3]);
            float2 v4 = unpack2(acc[j][4]), v5 = unpack2(acc[j][5]);
            float2 v6 = unpack2(acc[j][6]), v7 = unpack2(acc[j][7]);
            float cv0 = sC[r0], cv1 = sC[r0 + 1];
            if (cv0 != 0.0f) {
                const float* hp = g_h + (size_t)sSrc[r0] * DNF + c0;
                float4 h0 = ldcg4(hp);
                float4 h1 = ldcg4(hp + 4);
                float* dp = g_agg + (size_t)sDst[r0] * DNF + c0;
                red_add_v4(dp, (v0.x + bA.x) * cv0 * h0.x, (v1.x + bA.y) * cv0 * h0.y,
                               (v2.x + bA.z) * cv0 * h0.z, (v3.x + bA.w) * cv0 * h0.w);
                red_add_v4(dp + 4, (v4.x + bB.x) * cv0 * h1.x, (v5.x + bB.y) * cv0 * h1.y,
                                   (v6.x + bB.z) * cv0 * h1.z, (v7.x + bB.w) * cv0 * h1.w);
            }
            if (cv1 != 0.0f) {
                const float* hp = g_h + (size_t)sSrc[r0 + 1] * DNF + c0;
                float4 h0 = ldcg4(hp);
                float4 h1 = ldcg4(hp + 4);
                float* dp = g_agg + (size_t)sDst[r0 + 1] * DNF + c0;
                red_add_v4(dp, (v0.y + bA.x) * cv1 * h0.x, (v1.y + bA.y) * cv1 * h0.y,
                               (v2.y + bA.z) * cv1 * h0.z, (v3.y + bA.w) * cv1 * h0.w);
                red_add_v4(dp + 4, (v4.y + bB.x) * cv1 * h1.x, (v5.y + bB.y) * cv1 * h1.y,
                                   (v6.y + bB.z) * cv1 * h1.z, (v7.y + bB.w) * cv1 * h1.w);
            }
        }
    }
}

// -------- Kernel 3: out = ssp(agg@lin2_w + lin2_b) @ lin_w + lin_b --------
extern "C" __global__ void __launch_bounds__(256, 2)
k_out(const float* __restrict__ w2, const float* __restrict__ b2,
      const float* __restrict__ w3, const float* __restrict__ b3,
      float* __restrict__ out) {
    extern __shared__ float sm[];
    float* sA = sm;                   // 128*130 (aliased A then T)

    const int tid = threadIdx.x;
    const int cg = tid >> 4, rg = tid & 15;
    const int c0 = cg * 8, rg2 = rg * 2;

    const int ntiles = (NNODES + 127) / 128;
    for (int tile = blockIdx.x; tile < ntiles; tile += gridDim.x) {
        const int r0 = tile * 128;
        __syncthreads();
        {
            int e = tid >> 1, k0 = (tid & 1) << 6;
            int r = r0 + e;
            if (r < NNODES) {
                const float* src = g_agg + (size_t)r * DNF + k0;
#pragma unroll
                for (int i = 0; i < 16; ++i) {
                    float4 v = ldcs4(src + 4 * i);
                    int k = k0 + 4 * i;
                    sA[(k + 0) * 130 + e] = v.x;
                    sA[(k + 1) * 130 + e] = v.y;
                    sA[(k + 2) * 130 + e] = v.z;
                    sA[(k + 3) * 130 + e] = v.w;
                }
            } else {
#pragma unroll
                for (int i = 0; i < 16; ++i) {
                    int k = k0 + 4 * i;
                    sA[(k + 0) * 130 + e] = 0.f;
                    sA[(k + 1) * 130 + e] = 0.f;
                    sA[(k + 2) * 130 + e] = 0.f;
                    sA[(k + 3) * 130 + e] = 0.f;
                }
            }
        }
        __syncthreads();

        ull acc[4][8];
        zero_acc(acc);
        mm8x8g<DNF>(sA, w2, rg2, c0, acc);
        __syncthreads();   // all reads of sA done before overwrite as T

        {
            float4 bA = __ldg((const float4*)(b2 + c0));
            float4 bB = __ldg((const float4*)(b2 + c0 + 4));
            float bv[8] = {bA.x, bA.y, bA.z, bA.w, bB.x, bB.y, bB.z, bB.w};
#pragma unroll
            for (int c = 0; c < 8; ++c) {
#pragma unroll
                for (int j = 0; j < 4; ++j) {
                    float2 v = unpack2(acc[j][c]);
                    *(float2*)(sA + (c0 + c) * 130 + rg2 + 32 * j) =
                        make_float2(ssp_f(v.x + bv[c]), ssp_f(v.y + bv[c]));
                }
            }
        }
        __syncthreads();

        zero_acc(acc);
        mm8x8g<DHID>(sA, w3, rg2, c0, acc);

        float4 bA = __ldg((const float4*)(b3 + c0));
        float4 bB = __ldg((const float4*)(b3 + c0 + 4));

#pragma unroll
        for (int j = 0; j < 4; ++j) {
            int r = r0 + rg2 + 32 * j;
            float2 v0 = unpack2(acc[j][0]), v1 = unpack2(acc[j][1]);
            float2 v2 = unpack2(acc[j][2]), v3 = unpack2(acc[j][3]);
            float2 v4 = unpack2(acc[j][4]), v5 = unpack2(acc[j][5]);
            float2 v6 = unpack2(acc[j][6]), v7 = unpack2(acc[j][7]);
            if (r < NNODES) {
                *(float4*)(out + (size_t)r * DHID + c0) =
                    make_float4(v0.x + bA.x, v1.x + bA.y, v2.x + bA.z, v3.x + bA.w);
                *(float4*)(out + (size_t)r * DHID + c0 + 4) =
                    make_float4(v4.x + bB.x, v5.x + bB.y, v6.x + bB.z, v7.x + bB.w);
            }
            if (r + 1 < NNODES) {
                *(float4*)(out + (size_t)(r + 1) * DHID + c0) =
                    make_float4(v0.y + bA.x, v1.y + bA.y, v2.y + bA.z, v3.y + bA.w);
                *(float4*)(out + (size_t)(r + 1) * DHID + c0 + 4) =
                    make_float4(v4.y + bB.x, v5.y + bB.y, v6.y + bB.z, v7.y + bB.w);
            }
        }
    }
}

extern "C" void kernel_launch(void* const* d_in, const int* in_sizes, int n_in,
                              void* d_out, int out_size) {
    const float* x      = (const float*)d_in[0];
    const int*   ei     = (const int*)d_in[1];
    const float* elen   = (const float*)d_in[2];
    const float* eattr  = (const float*)d_in[3];
    const float* lin1_w = (const float*)d_in[4];
    const float* nn_w1  = (const float*)d_in[5];
    const float* nn_b1  = (const float*)d_in[6];
    const float* nn_w2  = (const float*)d_in[7];
    const float* nn_b2  = (const float*)d_in[8];
    const float* lin2_w = (const float*)d_in[9];
    const float* lin2_b = (const float*)d_in[10];
    const float* lin_w  = (const float*)d_in[11];
    const float* lin_b  = (const float*)d_in[12];
    float* out = (float*)d_out;

    size_t sm1 = (size_t)(DHID * 130) * 4;                  // 66560
    size_t sm2 = (size_t)(DNF * 130 + 3 * 128) * 4;         // 68096
    size_t sm3 = (size_t)(DNF * 130) * 4;                   // 66560

    cudaFuncSetAttribute(k_proj_zero, cudaFuncAttributeMaxDynamicSharedMemorySize, (int)sm1);
    cudaFuncSetAttribute(k_edge, cudaFuncAttributeMaxDynamicSharedMemorySize, (int)sm2);
    cudaFuncSetAttribute(k_out, cudaFuncAttributeMaxDynamicSharedMemorySize, (int)sm3);

    k_proj_zero<<<304, 256, sm1>>>(x, lin1_w);          // also zeroes g_cnt + g_agg
    k_compact<<<152, 256>>>(ei, elen);
    k_edge<<<304, 256, sm2>>>(eattr, nn_w1, nn_b1, nn_w2, nn_b2);
    k_out<<<304, 256, sm3>>>(lin2_w, lin2_b, lin_w, lin_b, out);
}